// round 8
// baseline (speedup 1.0000x reference)
#include <cuda_runtime.h>
#include <cuda_bf16.h>
#include <math.h>
#include <stdint.h>

#define BB 8
#define MM 2048
#define FF 128
#define NT 32
#define NITER (MM/NT)   // 64
#define MT 64

// ---- scratch ----
__device__ __nv_bfloat16 g_ht_hi[BB*FF*MM];  // h^T hi  [b][f][n]
__device__ __nv_bfloat16 g_ht_lo[BB*FF*MM];  // h^T lo
__device__ float2 g_rpA[BB*MM];              // (e^{s1}, e^{0.2 s1})
__device__ float2 g_rpB[BB*MM];              // (e^{s2}, e^{0.2 s2})

__device__ __forceinline__ void cp_async16(uint32_t dst, const void* src) {
    asm volatile("cp.async.cg.shared.global [%0], [%1], 16;" :: "r"(dst), "l"(src));
}

#define LDSM4(r, addr) \
    asm volatile("ldmatrix.sync.aligned.m8n8.x4.shared.b16 {%0,%1,%2,%3}, [%4];" \
        : "=r"((r)[0]), "=r"((r)[1]), "=r"((r)[2]), "=r"((r)[3]) : "r"(addr))

#define MMA16816(c, a, b0, b1) \
    asm volatile("mma.sync.aligned.m16n8k16.row.col.f32.bf16.bf16.f32 " \
        "{%0,%1,%2,%3}, {%4,%5,%6,%7}, {%8,%9}, {%0,%1,%2,%3};" \
        : "+f"((c)[0]), "+f"((c)[1]), "+f"((c)[2]), "+f"((c)[3]) \
        : "r"((a)[0]), "r"((a)[1]), "r"((a)[2]), "r"((a)[3]), "r"(b0), "r"(b1))

__device__ __forceinline__ uint32_t pack_bf16x2(float hi, float lo) {
    uint32_t u;
    asm("cvt.rn.bf16x2.f32 %0, %1, %2;" : "=r"(u) : "f"(hi), "f"(lo));
    return u;
}

// SMEM layout (dynamic):
//  [0, 20480)       w tiles: buf*10240 + comp*5120; 64 rows x 80B
//  [20480, 61440)   h tiles: buf*20480 + comp*10240; 128 rows x 80B
//  [61440, 61696)   den_s (64 f32)
#define SM_W     0
#define SM_H     20480
#define SM_DEN   61440
#define SM_TOT   61696
#define W_COMP   5120
#define W_BUF    10240
#define H_COMP   10240
#define H_BUF    20480

// ---------------------------------------------------------------------------
// K1: h = x@W; writes h^T (bf16 hi/lo) + per-row exp coefficients.
// grid (64, 8), block 256. CTA = 32 rows.
// ---------------------------------------------------------------------------
__global__ __launch_bounds__(256) void k_hgemm(const float* __restrict__ x,
                                               const float* __restrict__ W,
                                               const float* __restrict__ a)
{
    __shared__ float Ws[8192];
    __shared__ float xs[32][68];

    const int b   = blockIdx.y;
    const int m0  = blockIdx.x * 32;
    const int tid = threadIdx.x;
    const int row = tid >> 3;
    const int cg  = tid & 7;

    float acc[16];
#pragma unroll
    for (int j = 0; j < 16; j++) acc[j] = 0.f;

    const float* xb = x + ((size_t)b*MM + m0) * FF;

    for (int ch = 0; ch < 2; ch++) {
        const float4* Wv  = (const float4*)(W + ch*64*FF);
        float4*       Wsv = (float4*)Ws;
#pragma unroll
        for (int i = 0; i < 8; i++) Wsv[tid + i*256] = Wv[tid + i*256];
#pragma unroll
        for (int i = 0; i < 2; i++) {
            int idx = tid + i*256;
            int r = idx >> 4, q = (idx & 15) * 4;
            float4 v = *(const float4*)(xb + (size_t)r*FF + ch*64 + q);
            xs[r][q] = v.x; xs[r][q+1] = v.y; xs[r][q+2] = v.z; xs[r][q+3] = v.w;
        }
        __syncthreads();
#pragma unroll 8
        for (int i = 0; i < 64; i++) {
            float xv = xs[row][i];
#pragma unroll
            for (int t = 0; t < 4; t++)
#pragma unroll
                for (int j = 0; j < 4; j++)
                    acc[t*4+j] = fmaf(xv, Ws[i*128 + cg*4 + t*32 + j], acc[t*4+j]);
        }
        __syncthreads();
    }

    float p1 = 0.f, p2 = 0.f;
#pragma unroll
    for (int t = 0; t < 4; t++)
#pragma unroll
        for (int j = 0; j < 4; j++) {
            int col = cg*4 + t*32 + j;
            p1 = fmaf(acc[t*4+j], a[col],      p1);
            p2 = fmaf(acc[t*4+j], a[128+col],  p2);
        }
#pragma unroll
    for (int o = 4; o > 0; o >>= 1) {
        p1 += __shfl_down_sync(0xffffffffu, p1, o, 8);
        p2 += __shfl_down_sync(0xffffffffu, p2, o, 8);
    }
    if (cg == 0) {
        g_rpA[(size_t)b*MM + m0 + row] = make_float2(expf(p1), expf(0.2f*p1));
        g_rpB[(size_t)b*MM + m0 + row] = make_float2(expf(p2), expf(0.2f*p2));
    }

#pragma unroll
    for (int t = 0; t < 4; t++)
#pragma unroll
        for (int j = 0; j < 4; j++)
            Ws[row*130 + cg*4 + t*32 + j] = acc[t*4+j];
    __syncthreads();

    const int q  = tid & 7;
    const int fr = tid >> 3;
#pragma unroll
    for (int pass = 0; pass < 4; pass++) {
        int f = fr + 32*pass;
        float v0 = Ws[(q*4+0)*130 + f];
        float v1 = Ws[(q*4+1)*130 + f];
        float v2 = Ws[(q*4+2)*130 + f];
        float v3 = Ws[(q*4+3)*130 + f];
        __nv_bfloat16 h0 = __float2bfloat16_rn(v0);
        __nv_bfloat16 h1 = __float2bfloat16_rn(v1);
        __nv_bfloat16 h2 = __float2bfloat16_rn(v2);
        __nv_bfloat16 h3 = __float2bfloat16_rn(v3);
        uint32_t uh0 = (uint32_t)__bfloat16_as_ushort(h0) | ((uint32_t)__bfloat16_as_ushort(h1) << 16);
        uint32_t uh1 = (uint32_t)__bfloat16_as_ushort(h2) | ((uint32_t)__bfloat16_as_ushort(h3) << 16);
        uint32_t ul0 = pack_bf16x2(v1 - __bfloat162float(h1), v0 - __bfloat162float(h0));
        uint32_t ul1 = pack_bf16x2(v3 - __bfloat162float(h3), v2 - __bfloat162float(h2));
        size_t off = ((size_t)b*FF + f)*MM + m0 + q*4;
        *(uint2*)((char*)g_ht_hi + off*2) = make_uint2(uh0, uh1);
        *(uint2*)((char*)g_ht_lo + off*2) = make_uint2(ul0, ul1);
    }
}

// ---------------------------------------------------------------------------
// K2: warp-specialized masked attention. block 384 = 8 MMA warps + 4 producer
// warps. grid (32, 8), 2 CTAs/SM. CTA = 64 m-rows, n tiles of 32, double-buf.
// Consumer warp tile: wm = wid&1 (32 m), wf = wid>>1 (32 f).
// ---------------------------------------------------------------------------
__global__ __launch_bounds__(384, 2) void k_attn(const int* __restrict__ adj,
                                                 float* __restrict__ out)
{
    extern __shared__ char sm[];
    const uint32_t sbase = (uint32_t)__cvta_generic_to_shared(sm);
    float* den_s = (float*)(sm + SM_DEN);

    const int b    = blockIdx.y;
    const int m0   = blockIdx.x * MT;
    const int tid  = threadIdx.x;
    const int wid  = tid >> 5;
    const int lane = tid & 31;
    const bool is_prod = (wid >= 8);

    // ---------------- producer state ----------------
    const int ptid = tid - 256;          // 0..127 for producers
    const int pc   = ptid & 7;           // n quad
    const int pr   = ptid >> 3;          // row base (0..15); rows {pr+16i}
    float2 cc[4];
    float denp[4] = {0.f, 0.f, 0.f, 0.f};
    int4 adjv[4];
    const int* adjp = adj + ((size_t)(b*MM + m0 + pr))*MM + pc*4;

    if (is_prod) {
#pragma unroll
        for (int i = 0; i < 4; i++) {
            cc[i] = __ldg(&g_rpA[(size_t)b*MM + m0 + pr + 16*i]);
            adjv[i] = __ldg((const int4*)(adjp + (size_t)16*i*MM));
        }
    }

    // ---------------- consumer state ----------------
    const int wm = wid & 1;
    const int wf = wid >> 1;
    const uint32_t offA0 = (uint32_t)((wm*32 + (lane & 7) + ((lane >> 3) & 1)*8)*80
                                      + (lane >> 4)*16);
    const uint32_t offA1 = offA0 + 16*80;
    const uint32_t offB  = (uint32_t)((wf*32 + (lane & 7) + ((lane >= 16) ? 8 : 0))*80
                                      + ((lane >> 3) & 1)*16);
    float C[2][4][4];
#pragma unroll
    for (int i = 0; i < 2; i++)
#pragma unroll
        for (int j = 0; j < 4; j++)
#pragma unroll
            for (int k = 0; k < 4; k++) C[i][j][k] = 0.f;

    for (int it = 0; it <= NITER; it++) {
        if (is_prod) {
            if (it < NITER) {
                const int buf = it & 1;
                // stage h(it) into h buf
                {
                    const uint32_t hdst = sbase + SM_H + buf*H_BUF;
#pragma unroll
                    for (int e = 0; e < 8; e++) {
                        int id    = ptid + 128*e;
                        int comp  = id >> 9;
                        int f     = (id >> 2) & 127;
                        int chunk = id & 3;
                        const char* base = comp ? (const char*)g_ht_lo : (const char*)g_ht_hi;
                        const char* src  = base + (((size_t)b*FF + f)*MM + it*NT + chunk*8) * 2;
                        cp_async16(hdst + comp*H_COMP + f*80 + chunk*16, src);
                    }
                    asm volatile("cp.async.commit_group;");
                }
                // build w(it) into w buf
                {
                    const uint32_t wbase = sbase + SM_W + buf*W_BUF;
                    const float4* rb = (const float4*)(g_rpB + (size_t)b*MM + it*NT) + pc*2;
                    float4 v0 = __ldg(rb), v1 = __ldg(rb + 1);
#pragma unroll
                    for (int i = 0; i < 4; i++) {
                        int4 av = adjv[i];
                        int row = pr + 16*i;
                        float w0 = av.x ? fmaxf(cc[i].x*v0.x, cc[i].y*v0.y) : 0.f;
                        float w1 = av.y ? fmaxf(cc[i].x*v0.z, cc[i].y*v0.w) : 0.f;
                        float w2 = av.z ? fmaxf(cc[i].x*v1.x, cc[i].y*v1.y) : 0.f;
                        float w3 = av.w ? fmaxf(cc[i].x*v1.z, cc[i].y*v1.w) : 0.f;
                        denp[i] += (w0 + w1) + (w2 + w3);
                        __nv_bfloat16 h0 = __float2bfloat16_rn(w0);
                        __nv_bfloat16 h1 = __float2bfloat16_rn(w1);
                        __nv_bfloat16 h2 = __float2bfloat16_rn(w2);
                        __nv_bfloat16 h3 = __float2bfloat16_rn(w3);
                        uint32_t uh0 = (uint32_t)__bfloat16_as_ushort(h0) | ((uint32_t)__bfloat16_as_ushort(h1) << 16);
                        uint32_t uh1 = (uint32_t)__bfloat16_as_ushort(h2) | ((uint32_t)__bfloat16_as_ushort(h3) << 16);
                        uint32_t ul0 = pack_bf16x2(w1 - __bfloat162float(h1), w0 - __bfloat162float(h0));
                        uint32_t ul1 = pack_bf16x2(w3 - __bfloat162float(h3), w2 - __bfloat162float(h2));
                        uint32_t o = wbase + row*80 + pc*8;
                        asm volatile("st.shared.v2.b32 [%0], {%1,%2};" :: "r"(o), "r"(uh0), "r"(uh1));
                        asm volatile("st.shared.v2.b32 [%0], {%1,%2};" :: "r"(o + W_COMP), "r"(ul0), "r"(ul1));
                    }
                }
                // prefetch adj(it+1)
                {
                    const int tn = (it+1 < NITER) ? (it+1)*NT : 0;
#pragma unroll
                    for (int i = 0; i < 4; i++)
                        adjv[i] = __ldg((const int4*)(adjp + (size_t)16*i*MM + tn));
                }
                asm volatile("cp.async.wait_group 0;");
            }
        } else if (it > 0) {
            // consume buf (it-1)&1
            const int buf = (it-1) & 1;
            const uint32_t wbase = sbase + SM_W + buf*W_BUF;
            const uint32_t hbase = sbase + SM_H + buf*H_BUF;
#pragma unroll
            for (int ks = 0; ks < 2; ks++) {
                uint32_t Ah0[4], Al0[4], Ah1[4], Al1[4];
                LDSM4(Ah0, wbase + offA0 + ks*32);
                LDSM4(Al0, wbase + offA0 + ks*32 + W_COMP);
                LDSM4(Ah1, wbase + offA1 + ks*32);
                LDSM4(Al1, wbase + offA1 + ks*32 + W_COMP);
#pragma unroll
                for (int fs = 0; fs < 2; fs++) {
                    uint32_t baddr = hbase + offB + fs*(16*80) + ks*32;
                    uint32_t Bh[4], Bl[4];
                    LDSM4(Bh, baddr);
                    LDSM4(Bl, baddr + H_COMP);
                    MMA16816(C[0][2*fs],   Ah0, Bh[0], Bh[1]);
                    MMA16816(C[0][2*fs],   Ah0, Bl[0], Bl[1]);
                    MMA16816(C[0][2*fs],   Al0, Bh[0], Bh[1]);
                    MMA16816(C[0][2*fs+1], Ah0, Bh[2], Bh[3]);
                    MMA16816(C[0][2*fs+1], Ah0, Bl[2], Bl[3]);
                    MMA16816(C[0][2*fs+1], Al0, Bh[2], Bh[3]);
                    MMA16816(C[1][2*fs],   Ah1, Bh[0], Bh[1]);
                    MMA16816(C[1][2*fs],   Ah1, Bl[0], Bl[1]);
                    MMA16816(C[1][2*fs],   Al1, Bh[0], Bh[1]);
                    MMA16816(C[1][2*fs+1], Ah1, Bh[2], Bh[3]);
                    MMA16816(C[1][2*fs+1], Ah1, Bl[2], Bl[3]);
                    MMA16816(C[1][2*fs+1], Al1, Bh[2], Bh[3]);
                }
            }
        }
        __syncthreads();
    }

    // producers: finalize den
    if (is_prod) {
#pragma unroll
        for (int i = 0; i < 4; i++)
#pragma unroll
            for (int o = 4; o > 0; o >>= 1)
                denp[i] += __shfl_down_sync(0xffffffffu, denp[i], o, 8);
        if (pc == 0) {
#pragma unroll
            for (int i = 0; i < 4; i++) den_s[pr + 16*i] = denp[i];
        }
    }
    __syncthreads();

    // consumers: normalize + ELU + store
    if (!is_prod) {
        float* ob = out + ((size_t)b*MM + m0) * FF;
#pragma unroll
        for (int ms = 0; ms < 2; ms++) {
            const int R0 = wm*32 + ms*16 + (lane >> 2);
            const float inv0 = 1.0f / den_s[R0];
            const float inv1 = 1.0f / den_s[R0 + 8];
#pragma unroll
            for (int j = 0; j < 4; j++) {
                int f0 = wf*32 + j*8 + 2*(lane & 3);
                float e0 = C[ms][j][0] * inv0;
                float e1 = C[ms][j][1] * inv0;
                float e2 = C[ms][j][2] * inv1;
                float e3 = C[ms][j][3] * inv1;
                e0 = e0 > 0.f ? e0 : expm1f(e0);
                e1 = e1 > 0.f ? e1 : expm1f(e1);
                e2 = e2 > 0.f ? e2 : expm1f(e2);
                e3 = e3 > 0.f ? e3 : expm1f(e3);
                *(float2*)(ob + (size_t)R0*FF + f0)     = make_float2(e0, e1);
                *(float2*)(ob + (size_t)(R0+8)*FF + f0) = make_float2(e2, e3);
            }
        }
    }
}

extern "C" void kernel_launch(void* const* d_in, const int* in_sizes, int n_in,
                              void* d_out, int out_size)
{
    const float* x   = (const float*)d_in[0];
    const int*   adj = (const int*)d_in[1];
    const float* W   = (const float*)d_in[2];
    const float* a   = (const float*)d_in[3];
    float*       out = (float*)d_out;

    static int smem_set = 0;
    if (!smem_set) {
        cudaFuncSetAttribute(k_attn, cudaFuncAttributeMaxDynamicSharedMemorySize, SM_TOT);
        smem_set = 1;
    }

    k_hgemm<<<dim3(MM/32, BB), 256>>>(x, W, a);
    k_attn<<<dim3(MM/MT, BB), 384, SM_TOT>>>(adj, out);
}

// round 9
// speedup vs baseline: 1.1078x; 1.1078x over previous
#include <cuda_runtime.h>
#include <cuda_bf16.h>
#include <math.h>
#include <stdint.h>

#define BB 8
#define MM 2048
#define FF 128
#define NT 64
#define NITER (MM/NT)   // 32
#define MT 64

// ---- scratch ----
__device__ __nv_bfloat16 g_ht_hi[BB*FF*MM];  // h^T hi  [b][f][n]
__device__ __nv_bfloat16 g_ht_lo[BB*FF*MM];  // h^T lo
__device__ float2 g_rpA[BB*MM];              // (e^{s1}, e^{0.2 s1})
__device__ float2 g_rpB[BB*MM];              // (e^{s2}, e^{0.2 s2})

__device__ __forceinline__ void cp_async16(uint32_t dst, const void* src) {
    asm volatile("cp.async.cg.shared.global [%0], [%1], 16;" :: "r"(dst), "l"(src));
}

#define LDSM4(r, addr) \
    asm volatile("ldmatrix.sync.aligned.m8n8.x4.shared.b16 {%0,%1,%2,%3}, [%4];" \
        : "=r"((r)[0]), "=r"((r)[1]), "=r"((r)[2]), "=r"((r)[3]) : "r"(addr))

#define MMA16816(c, a, b0, b1) \
    asm volatile("mma.sync.aligned.m16n8k16.row.col.f32.bf16.bf16.f32 " \
        "{%0,%1,%2,%3}, {%4,%5,%6,%7}, {%8,%9}, {%0,%1,%2,%3};" \
        : "+f"((c)[0]), "+f"((c)[1]), "+f"((c)[2]), "+f"((c)[3]) \
        : "r"((a)[0]), "r"((a)[1]), "r"((a)[2]), "r"((a)[3]), "r"(b0), "r"(b1))

__device__ __forceinline__ uint32_t pack_bf16x2(float hi, float lo) {
    uint32_t u;
    asm("cvt.rn.bf16x2.f32 %0, %1, %2;" : "=r"(u) : "f"(hi), "f"(lo));
    return u;
}

// SMEM layout (dynamic), 144B rows (128B data + 16 pad, ldmatrix conflict-free):
//  w tiles: [buf][comp][64 rows x 144B]   2*2*9216  = 36864
//  h tiles: [buf][comp][128 rows x 144B]  2*2*18432 = 73728
//  den_s: 64 f32
#define W_COMP   9216
#define W_BUF    18432
#define SM_H     36864
#define H_COMP   18432
#define H_BUF    36864
#define SM_DEN   110592
#define SM_TOT   110848

// ---------------------------------------------------------------------------
// K1: h = x@W; writes h^T (bf16 hi/lo) + per-row exp coefficients.
// grid (64, 8), block 256. CTA = 32 rows.  (unchanged from R6)
// ---------------------------------------------------------------------------
__global__ __launch_bounds__(256) void k_hgemm(const float* __restrict__ x,
                                               const float* __restrict__ W,
                                               const float* __restrict__ a)
{
    __shared__ float Ws[8192];
    __shared__ float xs[32][68];

    const int b   = blockIdx.y;
    const int m0  = blockIdx.x * 32;
    const int tid = threadIdx.x;
    const int row = tid >> 3;
    const int cg  = tid & 7;

    float acc[16];
#pragma unroll
    for (int j = 0; j < 16; j++) acc[j] = 0.f;

    const float* xb = x + ((size_t)b*MM + m0) * FF;

    for (int ch = 0; ch < 2; ch++) {
        const float4* Wv  = (const float4*)(W + ch*64*FF);
        float4*       Wsv = (float4*)Ws;
#pragma unroll
        for (int i = 0; i < 8; i++) Wsv[tid + i*256] = Wv[tid + i*256];
#pragma unroll
        for (int i = 0; i < 2; i++) {
            int idx = tid + i*256;
            int r = idx >> 4, q = (idx & 15) * 4;
            float4 v = *(const float4*)(xb + (size_t)r*FF + ch*64 + q);
            xs[r][q] = v.x; xs[r][q+1] = v.y; xs[r][q+2] = v.z; xs[r][q+3] = v.w;
        }
        __syncthreads();
#pragma unroll 8
        for (int i = 0; i < 64; i++) {
            float xv = xs[row][i];
#pragma unroll
            for (int t = 0; t < 4; t++)
#pragma unroll
                for (int j = 0; j < 4; j++)
                    acc[t*4+j] = fmaf(xv, Ws[i*128 + cg*4 + t*32 + j], acc[t*4+j]);
        }
        __syncthreads();
    }

    float p1 = 0.f, p2 = 0.f;
#pragma unroll
    for (int t = 0; t < 4; t++)
#pragma unroll
        for (int j = 0; j < 4; j++) {
            int col = cg*4 + t*32 + j;
            p1 = fmaf(acc[t*4+j], a[col],      p1);
            p2 = fmaf(acc[t*4+j], a[128+col],  p2);
        }
#pragma unroll
    for (int o = 4; o > 0; o >>= 1) {
        p1 += __shfl_down_sync(0xffffffffu, p1, o, 8);
        p2 += __shfl_down_sync(0xffffffffu, p2, o, 8);
    }
    if (cg == 0) {
        g_rpA[(size_t)b*MM + m0 + row] = make_float2(expf(p1), expf(0.2f*p1));
        g_rpB[(size_t)b*MM + m0 + row] = make_float2(expf(p2), expf(0.2f*p2));
    }

#pragma unroll
    for (int t = 0; t < 4; t++)
#pragma unroll
        for (int j = 0; j < 4; j++)
            Ws[row*130 + cg*4 + t*32 + j] = acc[t*4+j];
    __syncthreads();

    const int q  = tid & 7;
    const int fr = tid >> 3;
#pragma unroll
    for (int pass = 0; pass < 4; pass++) {
        int f = fr + 32*pass;
        float v0 = Ws[(q*4+0)*130 + f];
        float v1 = Ws[(q*4+1)*130 + f];
        float v2 = Ws[(q*4+2)*130 + f];
        float v3 = Ws[(q*4+3)*130 + f];
        __nv_bfloat16 h0 = __float2bfloat16_rn(v0);
        __nv_bfloat16 h1 = __float2bfloat16_rn(v1);
        __nv_bfloat16 h2 = __float2bfloat16_rn(v2);
        __nv_bfloat16 h3 = __float2bfloat16_rn(v3);
        uint32_t uh0 = (uint32_t)__bfloat16_as_ushort(h0) | ((uint32_t)__bfloat16_as_ushort(h1) << 16);
        uint32_t uh1 = (uint32_t)__bfloat16_as_ushort(h2) | ((uint32_t)__bfloat16_as_ushort(h3) << 16);
        uint32_t ul0 = pack_bf16x2(v1 - __bfloat162float(h1), v0 - __bfloat162float(h0));
        uint32_t ul1 = pack_bf16x2(v3 - __bfloat162float(h3), v2 - __bfloat162float(h2));
        size_t off = ((size_t)b*FF + f)*MM + m0 + q*4;
        *(uint2*)((char*)g_ht_hi + off*2) = make_uint2(uh0, uh1);
        *(uint2*)((char*)g_ht_lo + off*2) = make_uint2(ul0, ul1);
    }
}

// ---------------------------------------------------------------------------
// stage one 64-n h tile (hi+lo): 2048 x 16B chunks, 8 per thread.
// ---------------------------------------------------------------------------
__device__ __forceinline__ void stage_h(uint32_t hdst, int b, int n0, int tid)
{
#pragma unroll
    for (int e = 0; e < 8; e++) {
        int id    = tid + 256*e;       // 0..2047
        int comp  = id >> 10;
        int cid   = id & 1023;
        int f     = cid >> 3;
        int chunk = cid & 7;
        const char* base = comp ? (const char*)g_ht_lo : (const char*)g_ht_hi;
        const char* src  = base + (((size_t)b*FF + f)*MM + n0 + chunk*8) * 2;
        cp_async16(hdst + comp*H_COMP + f*144 + chunk*16, src);
    }
    asm volatile("cp.async.commit_group;");
}

// ---------------------------------------------------------------------------
// K2: fused masked attention, interleaved build/MMA, warp-parity ordering.
// grid (32, 8), block 256 (8 warps), 2 CTAs/SM. CTA = 64 m x 128 f, NT=64.
// Build map: pc = tid&15 (n quad), pr = tid>>4 -> rows {pr+16i}.
// MMA map: wm = wid&1 (32 m), wf = wid>>1 (32 f).
// ---------------------------------------------------------------------------
__global__ __launch_bounds__(256, 2) void k_attn(const int* __restrict__ adj,
                                                 float* __restrict__ out)
{
    extern __shared__ char sm[];
    const uint32_t sbase = (uint32_t)__cvta_generic_to_shared(sm);
    float* den_s = (float*)(sm + SM_DEN);

    const int b    = blockIdx.y;
    const int m0   = blockIdx.x * MT;
    const int tid  = threadIdx.x;
    const int wid  = tid >> 5;
    const int lane = tid & 31;

    const int pc = tid & 15;
    const int pr = tid >> 4;

    float2 cc[4];
    float denp[4] = {0.f, 0.f, 0.f, 0.f};
    int4 adjv[4];
    const int* adjp = adj + ((size_t)(b*MM + m0 + pr))*MM + pc*4;
#pragma unroll
    for (int i = 0; i < 4; i++) {
        cc[i] = __ldg(&g_rpA[(size_t)b*MM + m0 + pr + 16*i]);
        adjv[i] = __ldg((const int4*)(adjp + (size_t)16*i*MM));
    }

    const int wm = wid & 1;
    const int wf = wid >> 1;
    const uint32_t offA0 = (uint32_t)((wm*32 + (lane & 7) + ((lane >> 3) & 1)*8)*144
                                      + (lane >> 4)*16);
    const uint32_t offA1 = offA0 + 16*144;
    const uint32_t offB  = (uint32_t)((wf*32 + (lane & 7) + ((lane >= 16) ? 8 : 0))*144
                                      + ((lane >> 3) & 1)*16);
    float C[2][4][4];
#pragma unroll
    for (int i = 0; i < 2; i++)
#pragma unroll
        for (int j = 0; j < 4; j++)
#pragma unroll
            for (int k = 0; k < 4; k++) C[i][j][k] = 0.f;

    // builds tile `tt` into buffer tt&1 (uses adjv, which must hold tile tt)
    auto build_w = [&](int tt) {
        const uint32_t wbase = sbase + (tt & 1)*W_BUF;
        const float4* rb = (const float4*)(g_rpB + (size_t)b*MM + tt*NT) + pc*2;
        float4 v0 = __ldg(rb), v1 = __ldg(rb + 1);
#pragma unroll
        for (int i = 0; i < 4; i++) {
            int4 av = adjv[i];
            int row = pr + 16*i;
            float w0 = av.x ? fmaxf(cc[i].x*v0.x, cc[i].y*v0.y) : 0.f;
            float w1 = av.y ? fmaxf(cc[i].x*v0.z, cc[i].y*v0.w) : 0.f;
            float w2 = av.z ? fmaxf(cc[i].x*v1.x, cc[i].y*v1.y) : 0.f;
            float w3 = av.w ? fmaxf(cc[i].x*v1.z, cc[i].y*v1.w) : 0.f;
            denp[i] += (w0 + w1) + (w2 + w3);
            __nv_bfloat16 h0 = __float2bfloat16_rn(w0);
            __nv_bfloat16 h1 = __float2bfloat16_rn(w1);
            __nv_bfloat16 h2 = __float2bfloat16_rn(w2);
            __nv_bfloat16 h3 = __float2bfloat16_rn(w3);
            uint32_t uh0 = (uint32_t)__bfloat16_as_ushort(h0) | ((uint32_t)__bfloat16_as_ushort(h1) << 16);
            uint32_t uh1 = (uint32_t)__bfloat16_as_ushort(h2) | ((uint32_t)__bfloat16_as_ushort(h3) << 16);
            uint32_t ul0 = pack_bf16x2(w1 - __bfloat162float(h1), w0 - __bfloat162float(h0));
            uint32_t ul1 = pack_bf16x2(w3 - __bfloat162float(h3), w2 - __bfloat162float(h2));
            uint32_t o = wbase + row*144 + pc*8;
            asm volatile("st.shared.v2.b32 [%0], {%1,%2};" :: "r"(o), "r"(uh0), "r"(uh1));
            asm volatile("st.shared.v2.b32 [%0], {%1,%2};" :: "r"(o + W_COMP), "r"(ul0), "r"(ul1));
        }
    };

    auto prefetch_adj = [&](int tt) {
        const int tn = (tt < NITER) ? tt*NT : 0;
#pragma unroll
        for (int i = 0; i < 4; i++)
            adjv[i] = __ldg((const int4*)(adjp + (size_t)16*i*MM + tn));
    };

    auto do_mma = [&](int tt) {
        const uint32_t wbase = sbase + (tt & 1)*W_BUF;
        const uint32_t hbase = sbase + SM_H + (tt & 1)*H_BUF;
#pragma unroll
        for (int ks = 0; ks < 4; ks++) {
            uint32_t Ah0[4], Al0[4], Ah1[4], Al1[4];
            LDSM4(Ah0, wbase + offA0 + ks*32);
            LDSM4(Al0, wbase + offA0 + ks*32 + W_COMP);
            LDSM4(Ah1, wbase + offA1 + ks*32);
            LDSM4(Al1, wbase + offA1 + ks*32 + W_COMP);
#pragma unroll
            for (int fs = 0; fs < 2; fs++) {
                uint32_t baddr = hbase + offB + fs*(16*144) + ks*32;
                uint32_t Bh[4], Bl[4];
                LDSM4(Bh, baddr);
                LDSM4(Bl, baddr + H_COMP);
                MMA16816(C[0][2*fs],   Ah0, Bh[0], Bh[1]);
                MMA16816(C[0][2*fs],   Ah0, Bl[0], Bl[1]);
                MMA16816(C[0][2*fs],   Al0, Bh[0], Bh[1]);
                MMA16816(C[0][2*fs+1], Ah0, Bh[2], Bh[3]);
                MMA16816(C[0][2*fs+1], Ah0, Bl[2], Bl[3]);
                MMA16816(C[0][2*fs+1], Al0, Bh[2], Bh[3]);
                MMA16816(C[1][2*fs],   Ah1, Bh[0], Bh[1]);
                MMA16816(C[1][2*fs],   Ah1, Bl[0], Bl[1]);
                MMA16816(C[1][2*fs],   Al1, Bh[0], Bh[1]);
                MMA16816(C[1][2*fs+1], Ah1, Bh[2], Bh[3]);
                MMA16816(C[1][2*fs+1], Ah1, Bl[2], Bl[3]);
                MMA16816(C[1][2*fs+1], Al1, Bh[2], Bh[3]);
            }
        }
    };

    // prologue: tile 0 into buf 0
    stage_h(sbase + SM_H, b, 0, tid);
    build_w(0);
    prefetch_adj(1);
    asm volatile("cp.async.wait_group 0;");
    __syncthreads();

    for (int t = 0; t < NITER; t++) {
        const bool more = (t + 1 < NITER);
        if (more)
            stage_h(sbase + SM_H + ((t+1) & 1)*H_BUF, b, (t+1)*NT, tid);
        // interleave: even warps MMA first (feed tensor pipe at barrier release),
        // odd warps build first; work is data-independent.
        if (wid & 1) {
            if (more) { build_w(t+1); prefetch_adj(t+2); }
            do_mma(t);
        } else {
            do_mma(t);
            if (more) { build_w(t+1); prefetch_adj(t+2); }
        }
        if (more)
            asm volatile("cp.async.wait_group 0;");
        __syncthreads();
    }

    // den reduce over the 16 pc-lanes sharing each row
#pragma unroll
    for (int i = 0; i < 4; i++)
#pragma unroll
        for (int o = 8; o > 0; o >>= 1)
            denp[i] += __shfl_down_sync(0xffffffffu, denp[i], o, 16);
    if (pc == 0) {
#pragma unroll
        for (int i = 0; i < 4; i++) den_s[pr + 16*i] = denp[i];
    }
    __syncthreads();

    // epilogue: normalize + ELU + store
    float* ob = out + ((size_t)b*MM + m0) * FF;
#pragma unroll
    for (int ms = 0; ms < 2; ms++) {
        const int R0 = wm*32 + ms*16 + (lane >> 2);
        const float inv0 = 1.0f / den_s[R0];
        const float inv1 = 1.0f / den_s[R0 + 8];
#pragma unroll
        for (int j = 0; j < 4; j++) {
            int f0 = wf*32 + j*8 + 2*(lane & 3);
            float e0 = C[ms][j][0] * inv0;
            float e1 = C[ms][j][1] * inv0;
            float e2 = C[ms][j][2] * inv1;
            float e3 = C[ms][j][3] * inv1;
            e0 = e0 > 0.f ? e0 : expm1f(e0);
            e1 = e1 > 0.f ? e1 : expm1f(e1);
            e2 = e2 > 0.f ? e2 : expm1f(e2);
            e3 = e3 > 0.f ? e3 : expm1f(e3);
            *(float2*)(ob + (size_t)R0*FF + f0)     = make_float2(e0, e1);
            *(float2*)(ob + (size_t)(R0+8)*FF + f0) = make_float2(e2, e3);
        }
    }
}

extern "C" void kernel_launch(void* const* d_in, const int* in_sizes, int n_in,
                              void* d_out, int out_size)
{
    const float* x   = (const float*)d_in[0];
    const int*   adj = (const int*)d_in[1];
    const float* W   = (const float*)d_in[2];
    const float* a   = (const float*)d_in[3];
    float*       out = (float*)d_out;

    static int smem_set = 0;
    if (!smem_set) {
        cudaFuncSetAttribute(k_attn, cudaFuncAttributeMaxDynamicSharedMemorySize, SM_TOT);
        smem_set = 1;
    }

    k_hgemm<<<dim3(MM/32, BB), 256>>>(x, W, a);
    k_attn<<<dim3(MM/MT, BB), 256, SM_TOT>>>(adj, out);
}

// round 10
// speedup vs baseline: 1.3049x; 1.1779x over previous
#include <cuda_runtime.h>
#include <cuda_fp16.h>
#include <math.h>
#include <stdint.h>

#define BB 8
#define MM 2048
#define FF 128
#define NT 64
#define NITER (MM/NT)   // 32
#define MT 64
#define WSCALE 0.015625f   // 2^-6: keeps w in fp16 range; cancels in num/den

// ---- scratch ----
__device__ __half g_ht_hi[BB*FF*MM];  // h^T hi  [b][f][n]
__device__ __half g_ht_lo[BB*FF*MM];  // h^T lo
__device__ float2 g_rpA[BB*MM];       // (e^{s1}, e^{0.2 s1})
__device__ float2 g_rpB[BB*MM];       // (e^{s2}, e^{0.2 s2})

__device__ __forceinline__ void cp_async16(uint32_t dst, const void* src) {
    asm volatile("cp.async.cg.shared.global [%0], [%1], 16;" :: "r"(dst), "l"(src));
}

#define LDSM4(r, addr) \
    asm volatile("ldmatrix.sync.aligned.m8n8.x4.shared.b16 {%0,%1,%2,%3}, [%4];" \
        : "=r"((r)[0]), "=r"((r)[1]), "=r"((r)[2]), "=r"((r)[3]) : "r"(addr))

#define MMAF16(c, a, b0, b1) \
    asm volatile("mma.sync.aligned.m16n8k16.row.col.f32.f16.f16.f32 " \
        "{%0,%1,%2,%3}, {%4,%5,%6,%7}, {%8,%9}, {%0,%1,%2,%3};" \
        : "+f"((c)[0]), "+f"((c)[1]), "+f"((c)[2]), "+f"((c)[3]) \
        : "r"((a)[0]), "r"((a)[1]), "r"((a)[2]), "r"((a)[3]), "r"(b0), "r"(b1))

// SMEM layout (144B rows = 128B data + 16 pad):
//  w tiles: [buf][64 x 144B]            2*9216  = 18432
//  h tiles: [buf][comp][128 x 144B]     2*2*18432 = 73728
//  den_s: 64 f32
#define W_BUF    9216
#define SM_H     18432
#define H_COMP   18432
#define H_BUF    36864
#define SM_DEN   92160
#define SM_TOT   92416

// ---------------------------------------------------------------------------
// K1: h = x@W; writes h^T (fp16 hi/lo) + per-row exp coefficients.
// grid (64, 8), block 256. CTA = 32 rows.
// ---------------------------------------------------------------------------
__global__ __launch_bounds__(256) void k_hgemm(const float* __restrict__ x,
                                               const float* __restrict__ W,
                                               const float* __restrict__ a)
{
    __shared__ float Ws[8192];
    __shared__ float xs[32][68];

    const int b   = blockIdx.y;
    const int m0  = blockIdx.x * 32;
    const int tid = threadIdx.x;
    const int row = tid >> 3;
    const int cg  = tid & 7;

    float acc[16];
#pragma unroll
    for (int j = 0; j < 16; j++) acc[j] = 0.f;

    const float* xb = x + ((size_t)b*MM + m0) * FF;

    for (int ch = 0; ch < 2; ch++) {
        const float4* Wv  = (const float4*)(W + ch*64*FF);
        float4*       Wsv = (float4*)Ws;
#pragma unroll
        for (int i = 0; i < 8; i++) Wsv[tid + i*256] = Wv[tid + i*256];
#pragma unroll
        for (int i = 0; i < 2; i++) {
            int idx = tid + i*256;
            int r = idx >> 4, q = (idx & 15) * 4;
            float4 v = *(const float4*)(xb + (size_t)r*FF + ch*64 + q);
            xs[r][q] = v.x; xs[r][q+1] = v.y; xs[r][q+2] = v.z; xs[r][q+3] = v.w;
        }
        __syncthreads();
#pragma unroll 8
        for (int i = 0; i < 64; i++) {
            float xv = xs[row][i];
#pragma unroll
            for (int t = 0; t < 4; t++)
#pragma unroll
                for (int j = 0; j < 4; j++)
                    acc[t*4+j] = fmaf(xv, Ws[i*128 + cg*4 + t*32 + j], acc[t*4+j]);
        }
        __syncthreads();
    }

    float p1 = 0.f, p2 = 0.f;
#pragma unroll
    for (int t = 0; t < 4; t++)
#pragma unroll
        for (int j = 0; j < 4; j++) {
            int col = cg*4 + t*32 + j;
            p1 = fmaf(acc[t*4+j], a[col],      p1);
            p2 = fmaf(acc[t*4+j], a[128+col],  p2);
        }
#pragma unroll
    for (int o = 4; o > 0; o >>= 1) {
        p1 += __shfl_down_sync(0xffffffffu, p1, o, 8);
        p2 += __shfl_down_sync(0xffffffffu, p2, o, 8);
    }
    if (cg == 0) {
        g_rpA[(size_t)b*MM + m0 + row] = make_float2(expf(p1), expf(0.2f*p1));
        g_rpB[(size_t)b*MM + m0 + row] = make_float2(expf(p2), expf(0.2f*p2));
    }

#pragma unroll
    for (int t = 0; t < 4; t++)
#pragma unroll
        for (int j = 0; j < 4; j++)
            Ws[row*130 + cg*4 + t*32 + j] = acc[t*4+j];
    __syncthreads();

    const int q  = tid & 7;
    const int fr = tid >> 3;
#pragma unroll
    for (int pass = 0; pass < 4; pass++) {
        int f = fr + 32*pass;
        float v0 = Ws[(q*4+0)*130 + f];
        float v1 = Ws[(q*4+1)*130 + f];
        float v2 = Ws[(q*4+2)*130 + f];
        float v3 = Ws[(q*4+3)*130 + f];
        __half h0 = __float2half_rn(v0);
        __half h1 = __float2half_rn(v1);
        __half h2 = __float2half_rn(v2);
        __half h3 = __float2half_rn(v3);
        __half2 hi01 = __halves2half2(h0, h1);
        __half2 hi23 = __halves2half2(h2, h3);
        __half2 lo01 = __floats2half2_rn(v0 - __half2float(h0), v1 - __half2float(h1));
        __half2 lo23 = __floats2half2_rn(v2 - __half2float(h2), v3 - __half2float(h3));
        size_t off = ((size_t)b*FF + f)*MM + m0 + q*4;
        *(uint2*)((char*)g_ht_hi + off*2) = make_uint2(*(uint32_t*)&hi01, *(uint32_t*)&hi23);
        *(uint2*)((char*)g_ht_lo + off*2) = make_uint2(*(uint32_t*)&lo01, *(uint32_t*)&lo23);
    }
}

// ---------------------------------------------------------------------------
// stage one 64-n h tile (hi+lo): 2048 x 16B chunks, 8 per thread.
// ---------------------------------------------------------------------------
__device__ __forceinline__ void stage_h(uint32_t hdst, int b, int n0, int tid)
{
#pragma unroll
    for (int e = 0; e < 8; e++) {
        int id    = tid + 256*e;       // 0..2047
        int comp  = id >> 10;
        int cid   = id & 1023;
        int f     = cid >> 3;
        int chunk = cid & 7;
        const char* base = comp ? (const char*)g_ht_lo : (const char*)g_ht_hi;
        const char* src  = base + (((size_t)b*FF + f)*MM + n0 + chunk*8) * 2;
        cp_async16(hdst + comp*H_COMP + f*144 + chunk*16, src);
    }
    asm volatile("cp.async.commit_group;");
}

// ---------------------------------------------------------------------------
// K2: fused masked attention, fp16 2-pass MMA, interleaved build/MMA.
// grid (32, 8), block 256 (8 warps), 2 CTAs/SM. CTA = 64 m x 128 f, NT=64.
// Build map: pc = tid&15 (n quad), pr = tid>>4 -> rows {pr+16i}.
// MMA map: wm = wid&1 (32 m), wf = wid>>1 (32 f).
// ---------------------------------------------------------------------------
__global__ __launch_bounds__(256, 2) void k_attn(const int* __restrict__ adj,
                                                 float* __restrict__ out)
{
    extern __shared__ char sm[];
    const uint32_t sbase = (uint32_t)__cvta_generic_to_shared(sm);
    float* den_s = (float*)(sm + SM_DEN);

    const int b    = blockIdx.y;
    const int m0   = blockIdx.x * MT;
    const int tid  = threadIdx.x;
    const int wid  = tid >> 5;
    const int lane = tid & 31;

    const int pc = tid & 15;
    const int pr = tid >> 4;

    float2 cc[4];
    float denp[4] = {0.f, 0.f, 0.f, 0.f};
    int4 adjv[4];
    const int* adjp = adj + ((size_t)(b*MM + m0 + pr))*MM + pc*4;
#pragma unroll
    for (int i = 0; i < 4; i++) {
        cc[i] = __ldg(&g_rpA[(size_t)b*MM + m0 + pr + 16*i]);
        adjv[i] = __ldg((const int4*)(adjp + (size_t)16*i*MM));
    }

    const int wm = wid & 1;
    const int wf = wid >> 1;
    const uint32_t offA0 = (uint32_t)((wm*32 + (lane & 7) + ((lane >> 3) & 1)*8)*144
                                      + (lane >> 4)*16);
    const uint32_t offA1 = offA0 + 16*144;
    const uint32_t offB  = (uint32_t)((wf*32 + (lane & 7) + ((lane >= 16) ? 8 : 0))*144
                                      + ((lane >> 3) & 1)*16);
    float C[2][4][4];
#pragma unroll
    for (int i = 0; i < 2; i++)
#pragma unroll
        for (int j = 0; j < 4; j++)
#pragma unroll
            for (int k = 0; k < 4; k++) C[i][j][k] = 0.f;

    // build tile tt into w buffer tt&1 (adjv must hold tile tt)
    auto build_w = [&](int tt) {
        const uint32_t wbase = sbase + (tt & 1)*W_BUF;
        const float4* rb = (const float4*)(g_rpB + (size_t)b*MM + tt*NT) + pc*2;
        float4 v0 = __ldg(rb), v1 = __ldg(rb + 1);
#pragma unroll
        for (int i = 0; i < 4; i++) {
            int4 av = adjv[i];
            int row = pr + 16*i;
            float w0 = av.x ? fmaxf(cc[i].x*v0.x, cc[i].y*v0.y)*WSCALE : 0.f;
            float w1 = av.y ? fmaxf(cc[i].x*v0.z, cc[i].y*v0.w)*WSCALE : 0.f;
            float w2 = av.z ? fmaxf(cc[i].x*v1.x, cc[i].y*v1.y)*WSCALE : 0.f;
            float w3 = av.w ? fmaxf(cc[i].x*v1.z, cc[i].y*v1.w)*WSCALE : 0.f;
            __half2 q01 = __floats2half2_rn(w0, w1);
            __half2 q23 = __floats2half2_rn(w2, w3);
            // den from the QUANTIZED scaled weights -> num/den ratio exact
            float2 f01 = __half22float2(q01);
            float2 f23 = __half22float2(q23);
            denp[i] += (f01.x + f01.y) + (f23.x + f23.y);
            uint32_t u0 = *(uint32_t*)&q01;
            uint32_t u1 = *(uint32_t*)&q23;
            uint32_t o = wbase + row*144 + pc*8;
            asm volatile("st.shared.v2.b32 [%0], {%1,%2};" :: "r"(o), "r"(u0), "r"(u1));
        }
    };

    auto prefetch_adj = [&](int tt) {
        const int tn = (tt < NITER) ? tt*NT : 0;
#pragma unroll
        for (int i = 0; i < 4; i++)
            adjv[i] = __ldg((const int4*)(adjp + (size_t)16*i*MM + tn));
    };

    auto do_mma = [&](int tt) {
        const uint32_t wbase = sbase + (tt & 1)*W_BUF;
        const uint32_t hbase = sbase + SM_H + (tt & 1)*H_BUF;
#pragma unroll
        for (int ks = 0; ks < 4; ks++) {
            uint32_t A0[4], A1[4];
            LDSM4(A0, wbase + offA0 + ks*32);
            LDSM4(A1, wbase + offA1 + ks*32);
#pragma unroll
            for (int fs = 0; fs < 2; fs++) {
                uint32_t baddr = hbase + offB + fs*(16*144) + ks*32;
                uint32_t Bh[4], Bl[4];
                LDSM4(Bh, baddr);
                LDSM4(Bl, baddr + H_COMP);
                MMAF16(C[0][2*fs],   A0, Bh[0], Bh[1]);
                MMAF16(C[0][2*fs],   A0, Bl[0], Bl[1]);
                MMAF16(C[0][2*fs+1], A0, Bh[2], Bh[3]);
                MMAF16(C[0][2*fs+1], A0, Bl[2], Bl[3]);
                MMAF16(C[1][2*fs],   A1, Bh[0], Bh[1]);
                MMAF16(C[1][2*fs],   A1, Bl[0], Bl[1]);
                MMAF16(C[1][2*fs+1], A1, Bh[2], Bh[3]);
                MMAF16(C[1][2*fs+1], A1, Bl[2], Bl[3]);
            }
        }
    };

    // prologue: tile 0 into buf 0
    stage_h(sbase + SM_H, b, 0, tid);
    build_w(0);
    prefetch_adj(1);
    asm volatile("cp.async.wait_group 0;");
    __syncthreads();

    for (int t = 0; t < NITER; t++) {
        const bool more = (t + 1 < NITER);
        if (more)
            stage_h(sbase + SM_H + ((t+1) & 1)*H_BUF, b, (t+1)*NT, tid);
        if (wid & 1) {
            if (more) { build_w(t+1); prefetch_adj(t+2); }
            do_mma(t);
        } else {
            do_mma(t);
            if (more) { build_w(t+1); prefetch_adj(t+2); }
        }
        if (more)
            asm volatile("cp.async.wait_group 0;");
        __syncthreads();
    }

    // den reduce over the 16 pc-lanes sharing each row
#pragma unroll
    for (int i = 0; i < 4; i++)
#pragma unroll
        for (int o = 8; o > 0; o >>= 1)
            denp[i] += __shfl_down_sync(0xffffffffu, denp[i], o, 16);
    if (pc == 0) {
#pragma unroll
        for (int i = 0; i < 4; i++) den_s[pr + 16*i] = denp[i];
    }
    __syncthreads();

    // epilogue: normalize + ELU + store (scale cancels in num/den)
    float* ob = out + ((size_t)b*MM + m0) * FF;
#pragma unroll
    for (int ms = 0; ms < 2; ms++) {
        const int R0 = wm*32 + ms*16 + (lane >> 2);
        const float inv0 = 1.0f / den_s[R0];
        const float inv1 = 1.0f / den_s[R0 + 8];
#pragma unroll
        for (int j = 0; j < 4; j++) {
            int f0 = wf*32 + j*8 + 2*(lane & 3);
            float e0 = C[ms][j][0] * inv0;
            float e1 = C[ms][j][1] * inv0;
            float e2 = C[ms][j][2] * inv1;
            float e3 = C[ms][j][3] * inv1;
            e0 = e0 > 0.f ? e0 : expm1f(e0);
            e1 = e1 > 0.f ? e1 : expm1f(e1);
            e2 = e2 > 0.f ? e2 : expm1f(e2);
            e3 = e3 > 0.f ? e3 : expm1f(e3);
            *(float2*)(ob + (size_t)R0*FF + f0)     = make_float2(e0, e1);
            *(float2*)(ob + (size_t)(R0+8)*FF + f0) = make_float2(e2, e3);
        }
    }
}

extern "C" void kernel_launch(void* const* d_in, const int* in_sizes, int n_in,
                              void* d_out, int out_size)
{
    const float* x   = (const float*)d_in[0];
    const int*   adj = (const int*)d_in[1];
    const float* W   = (const float*)d_in[2];
    const float* a   = (const float*)d_in[3];
    float*       out = (float*)d_out;

    static int smem_set = 0;
    if (!smem_set) {
        cudaFuncSetAttribute(k_attn, cudaFuncAttributeMaxDynamicSharedMemorySize, SM_TOT);
        smem_set = 1;
    }

    k_hgemm<<<dim3(MM/32, BB), 256>>>(x, W, a);
    k_attn<<<dim3(MM/MT, BB), 256, SM_TOT>>>(adj, out);
}

// round 13
// speedup vs baseline: 1.6601x; 1.2722x over previous
#include <cuda_runtime.h>
#include <cuda_fp16.h>
#include <math.h>
#include <stdint.h>

#define BB 8
#define MM 2048
#define FF 128
#define NT 64
#define NITER (MM/NT)   // 32
#define MT 64
#define WSCALE 0.015625f   // 2^-6: keeps w in fp16 range; cancels in num/den

// ---- scratch ----
__device__ __half g_ht[BB*FF*MM];     // h^T fp16  [b][f][n]
__device__ float2 g_rpA[BB*MM];       // (e^{s1}, e^{0.2 s1})
__device__ float2 g_rpB[BB*MM];       // (e^{s2}, e^{0.2 s2})

__device__ __forceinline__ void cp_async16(uint32_t dst, const void* src) {
    asm volatile("cp.async.cg.shared.global [%0], [%1], 16;" :: "r"(dst), "l"(src));
}

#define LDSM4(r, addr) \
    asm volatile("ldmatrix.sync.aligned.m8n8.x4.shared.b16 {%0,%1,%2,%3}, [%4];" \
        : "=r"((r)[0]), "=r"((r)[1]), "=r"((r)[2]), "=r"((r)[3]) : "r"(addr))

#define MMAF16(c, a, b0, b1) \
    asm volatile("mma.sync.aligned.m16n8k16.row.col.f32.f16.f16.f32 " \
        "{%0,%1,%2,%3}, {%4,%5,%6,%7}, {%8,%9}, {%0,%1,%2,%3};" \
        : "+f"((c)[0]), "+f"((c)[1]), "+f"((c)[2]), "+f"((c)[3]) \
        : "r"((a)[0]), "r"((a)[1]), "r"((a)[2]), "r"((a)[3]), "r"(b0), "r"(b1))

// SMEM layout (144B rows = 128B data + 16 pad):
//  w tiles: [buf][64 x 144B]    2*9216  = 18432
//  h tiles: [buf][128 x 144B]   2*18432 = 36864
//  den_s: 64 f32
#define W_BUF    9216
#define SM_H     18432
#define H_BUF    18432
#define SM_DEN   55296
#define SM_TOT   55552

// ---------------------------------------------------------------------------
// K1: h = x@W; writes h^T (fp16) + per-row exp coefficients.
// grid (64, 8), block 256. CTA = 32 rows.
// ---------------------------------------------------------------------------
__global__ __launch_bounds__(256) void k_hgemm(const float* __restrict__ x,
                                               const float* __restrict__ W,
                                               const float* __restrict__ a)
{
    __shared__ float Ws[8192];
    __shared__ float xs[32][68];

    const int b   = blockIdx.y;
    const int m0  = blockIdx.x * 32;
    const int tid = threadIdx.x;
    const int row = tid >> 3;
    const int cg  = tid & 7;

    float acc[16];
#pragma unroll
    for (int j = 0; j < 16; j++) acc[j] = 0.f;

    const float* xb = x + ((size_t)b*MM + m0) * FF;

    for (int ch = 0; ch < 2; ch++) {
        const float4* Wv  = (const float4*)(W + ch*64*FF);
        float4*       Wsv = (float4*)Ws;
#pragma unroll
        for (int i = 0; i < 8; i++) Wsv[tid + i*256] = Wv[tid + i*256];
#pragma unroll
        for (int i = 0; i < 2; i++) {
            int idx = tid + i*256;
            int r = idx >> 4, q = (idx & 15) * 4;
            float4 v = *(const float4*)(xb + (size_t)r*FF + ch*64 + q);
            xs[r][q] = v.x; xs[r][q+1] = v.y; xs[r][q+2] = v.z; xs[r][q+3] = v.w;
        }
        __syncthreads();
#pragma unroll 8
        for (int i = 0; i < 64; i++) {
            float xv = xs[row][i];
#pragma unroll
            for (int t = 0; t < 4; t++)
#pragma unroll
                for (int j = 0; j < 4; j++)
                    acc[t*4+j] = fmaf(xv, Ws[i*128 + cg*4 + t*32 + j], acc[t*4+j]);
        }
        __syncthreads();
    }

    float p1 = 0.f, p2 = 0.f;
#pragma unroll
    for (int t = 0; t < 4; t++)
#pragma unroll
        for (int j = 0; j < 4; j++) {
            int col = cg*4 + t*32 + j;
            p1 = fmaf(acc[t*4+j], a[col],      p1);
            p2 = fmaf(acc[t*4+j], a[128+col],  p2);
        }
#pragma unroll
    for (int o = 4; o > 0; o >>= 1) {
        p1 += __shfl_down_sync(0xffffffffu, p1, o, 8);
        p2 += __shfl_down_sync(0xffffffffu, p2, o, 8);
    }
    if (cg == 0) {
        g_rpA[(size_t)b*MM + m0 + row] = make_float2(expf(p1), expf(0.2f*p1));
        g_rpB[(size_t)b*MM + m0 + row] = make_float2(expf(p2), expf(0.2f*p2));
    }

#pragma unroll
    for (int t = 0; t < 4; t++)
#pragma unroll
        for (int j = 0; j < 4; j++)
            Ws[row*130 + cg*4 + t*32 + j] = acc[t*4+j];
    __syncthreads();

    const int q  = tid & 7;
    const int fr = tid >> 3;
#pragma unroll
    for (int pass = 0; pass < 4; pass++) {
        int f = fr + 32*pass;
        float v0 = Ws[(q*4+0)*130 + f];
        float v1 = Ws[(q*4+1)*130 + f];
        float v2 = Ws[(q*4+2)*130 + f];
        float v3 = Ws[(q*4+3)*130 + f];
        __half2 h01 = __floats2half2_rn(v0, v1);
        __half2 h23 = __floats2half2_rn(v2, v3);
        size_t off = ((size_t)b*FF + f)*MM + m0 + q*4;
        *(uint2*)((char*)g_ht + off*2) = make_uint2(*(uint32_t*)&h01, *(uint32_t*)&h23);
    }
}

// ---------------------------------------------------------------------------
// stage one 64-n h tile: 1024 x 16B chunks, 4 per thread.
// ---------------------------------------------------------------------------
__device__ __forceinline__ void stage_h(uint32_t hdst, int b, int n0, int tid)
{
#pragma unroll
    for (int e = 0; e < 4; e++) {
        int id    = tid + 256*e;       // 0..1023
        int f     = id >> 3;
        int chunk = id & 7;
        const char* src = (const char*)g_ht + (((size_t)b*FF + f)*MM + n0 + chunk*8) * 2;
        cp_async16(hdst + f*144 + chunk*16, src);
    }
    asm volatile("cp.async.commit_group;");
}

// ---------------------------------------------------------------------------
// K2: fused masked attention, fp16 1-pass MMA, interleaved build/MMA.
// grid (32, 8), block 256 (8 warps), 2 CTAs/SM. CTA = 64 m x 128 f, NT=64.
// Build map: pc = tid&15 (n quad), pr = tid>>4 -> rows {pr+16i}.
// MMA map: wm = wid&1 (32 m), wf = wid>>1 (32 f).
// ---------------------------------------------------------------------------
__global__ __launch_bounds__(256, 2) void k_attn(const int* __restrict__ adj,
                                                 float* __restrict__ out)
{
    extern __shared__ char sm[];
    const uint32_t sbase = (uint32_t)__cvta_generic_to_shared(sm);
    float* den_s = (float*)(sm + SM_DEN);

    const int b    = blockIdx.y;
    const int m0   = blockIdx.x * MT;
    const int tid  = threadIdx.x;
    const int wid  = tid >> 5;
    const int lane = tid & 31;

    const int pc = tid & 15;
    const int pr = tid >> 4;

    float2 cc[4];
    float denp[4] = {0.f, 0.f, 0.f, 0.f};
    int4 adjv[4];
    const int* adjp = adj + ((size_t)(b*MM + m0 + pr))*MM + pc*4;
#pragma unroll
    for (int i = 0; i < 4; i++) {
        cc[i] = __ldg(&g_rpA[(size_t)b*MM + m0 + pr + 16*i]);
        adjv[i] = __ldg((const int4*)(adjp + (size_t)16*i*MM));
    }

    const int wm = wid & 1;
    const int wf = wid >> 1;
    const uint32_t offA0 = (uint32_t)((wm*32 + (lane & 7) + ((lane >> 3) & 1)*8)*144
                                      + (lane >> 4)*16);
    const uint32_t offA1 = offA0 + 16*144;
    const uint32_t offB  = (uint32_t)((wf*32 + (lane & 7) + ((lane >= 16) ? 8 : 0))*144
                                      + ((lane >> 3) & 1)*16);
    float C[2][4][4];
#pragma unroll
    for (int i = 0; i < 2; i++)
#pragma unroll
        for (int j = 0; j < 4; j++)
#pragma unroll
            for (int k = 0; k < 4; k++) C[i][j][k] = 0.f;

    // build tile tt into w buffer tt&1 (adjv must hold tile tt)
    auto build_w = [&](int tt) {
        const uint32_t wbase = sbase + (tt & 1)*W_BUF;
        const float4* rb = (const float4*)(g_rpB + (size_t)b*MM + tt*NT) + pc*2;
        float4 v0 = __ldg(rb), v1 = __ldg(rb + 1);
#pragma unroll
        for (int i = 0; i < 4; i++) {
            int4 av = adjv[i];
            int row = pr + 16*i;
            float w0 = av.x ? fmaxf(cc[i].x*v0.x, cc[i].y*v0.y)*WSCALE : 0.f;
            float w1 = av.y ? fmaxf(cc[i].x*v0.z, cc[i].y*v0.w)*WSCALE : 0.f;
            float w2 = av.z ? fmaxf(cc[i].x*v1.x, cc[i].y*v1.y)*WSCALE : 0.f;
            float w3 = av.w ? fmaxf(cc[i].x*v1.z, cc[i].y*v1.w)*WSCALE : 0.f;
            __half2 q01 = __floats2half2_rn(w0, w1);
            __half2 q23 = __floats2half2_rn(w2, w3);
            // den from the QUANTIZED scaled weights -> num/den ratio consistent
            float2 f01 = __half22float2(q01);
            float2 f23 = __half22float2(q23);
            denp[i] += (f01.x + f01.y) + (f23.x + f23.y);
            uint32_t u0 = *(uint32_t*)&q01;
            uint32_t u1 = *(uint32_t*)&q23;
            uint32_t o = wbase + row*144 + pc*8;
            asm volatile("st.shared.v2.b32 [%0], {%1,%2};" :: "r"(o), "r"(u0), "r"(u1));
        }
    };

    auto prefetch_adj = [&](int tt) {
        const int tn = (tt < NITER) ? tt*NT : 0;
#pragma unroll
        for (int i = 0; i < 4; i++)
            adjv[i] = __ldg((const int4*)(adjp + (size_t)16*i*MM + tn));
    };

    auto do_mma = [&](int tt) {
        const uint32_t wbase = sbase + (tt & 1)*W_BUF;
        const uint32_t hbase = sbase + SM_H + (tt & 1)*H_BUF;
#pragma unroll
        for (int ks = 0; ks < 4; ks++) {
            uint32_t A0[4], A1[4];
            LDSM4(A0, wbase + offA0 + ks*32);
            LDSM4(A1, wbase + offA1 + ks*32);
#pragma unroll
            for (int fs = 0; fs < 2; fs++) {
                uint32_t B[4];
                LDSM4(B, hbase + offB + fs*(16*144) + ks*32);
                MMAF16(C[0][2*fs],   A0, B[0], B[1]);
                MMAF16(C[0][2*fs+1], A0, B[2], B[3]);
                MMAF16(C[1][2*fs],   A1, B[0], B[1]);
                MMAF16(C[1][2*fs+1], A1, B[2], B[3]);
            }
        }
    };

    // prologue: tile 0 into buf 0
    stage_h(sbase + SM_H, b, 0, tid);
    build_w(0);
    prefetch_adj(1);
    asm volatile("cp.async.wait_group 0;");
    __syncthreads();

    for (int t = 0; t < NITER; t++) {
        const bool more = (t + 1 < NITER);
        if (more)
            stage_h(sbase + SM_H + ((t+1) & 1)*H_BUF, b, (t+1)*NT, tid);
        if (wid & 1) {
            if (more) { build_w(t+1); prefetch_adj(t+2); }
            do_mma(t);
        } else {
            do_mma(t);
            if (more) { build_w(t+1); prefetch_adj(t+2); }
        }
        if (more)
            asm volatile("cp.async.wait_group 0;");
        __syncthreads();
    }

    // den reduce over the 16 pc-lanes sharing each row
#pragma unroll
    for (int i = 0; i < 4; i++)
#pragma unroll
        for (int o = 8; o > 0; o >>= 1)
            denp[i] += __shfl_down_sync(0xffffffffu, denp[i], o, 16);
    if (pc == 0) {
#pragma unroll
        for (int i = 0; i < 4; i++) den_s[pr + 16*i] = denp[i];
    }
    __syncthreads();

    // epilogue: normalize + ELU + store (scale cancels in num/den)
    float* ob = out + ((size_t)b*MM + m0) * FF;
#pragma unroll
    for (int ms = 0; ms < 2; ms++) {
        const int R0 = wm*32 + ms*16 + (lane >> 2);
        const float inv0 = 1.0f / den_s[R0];
        const float inv1 = 1.0f / den_s[R0 + 8];
#pragma unroll
        for (int j = 0; j < 4; j++) {
            int f0 = wf*32 + j*8 + 2*(lane & 3);
            float e0 = C[ms][j][0] * inv0;
            float e1 = C[ms][j][1] * inv0;
            float e2 = C[ms][j][2] * inv1;
            float e3 = C[ms][j][3] * inv1;
            e0 = e0 > 0.f ? e0 : expm1f(e0);
            e1 = e1 > 0.f ? e1 : expm1f(e1);
            e2 = e2 > 0.f ? e2 : expm1f(e2);
            e3 = e3 > 0.f ? e3 : expm1f(e3);
            *(float2*)(ob + (size_t)R0*FF + f0)     = make_float2(e0, e1);
            *(float2*)(ob + (size_t)(R0+8)*FF + f0) = make_float2(e2, e3);
        }
    }
}

extern "C" void kernel_launch(void* const* d_in, const int* in_sizes, int n_in,
                              void* d_out, int out_size)
{
    const float* x   = (const float*)d_in[0];
    const int*   adj = (const int*)d_in[1];
    const float* W   = (const float*)d_in[2];
    const float* a   = (const float*)d_in[3];
    float*       out = (float*)d_out;

    static int smem_set = 0;
    if (!smem_set) {
        cudaFuncSetAttribute(k_attn, cudaFuncAttributeMaxDynamicSharedMemorySize, SM_TOT);
        smem_set = 1;
    }

    k_hgemm<<<dim3(MM/32, BB), 256>>>(x, W, a);
    k_attn<<<dim3(MM/MT, BB), 256, SM_TOT>>>(adj, out);
}